// round 1
// baseline (speedup 1.0000x reference)
#include <cuda_runtime.h>
#include <cuda_bf16.h>

#define MROWS 4096
#define D_IN  512
#define D_HID 1024
#define D_OUT 512

// Scratch (no cudaMalloc allowed)
__device__ float g_h[MROWS * D_HID];
__device__ float g_sp[MROWS * D_HID];

// ---------------------------------------------------------------------------
// fp32 tiled GEMM: C[M,N] = A[M,K] @ B[K,N] + bias[N], optional ReLU
// BM=BN=64, BK=16, 256 threads, 4x4 per-thread microtile
// ---------------------------------------------------------------------------
template<bool RELU>
__global__ __launch_bounds__(256)
void gemm_bias_kernel(const float* __restrict__ A,
                      const float* __restrict__ B,
                      const float* __restrict__ bias,
                      float* __restrict__ C,
                      int N, int K)
{
    constexpr int BM = 64, BN = 64, BK = 16;
    __shared__ float As[BK][BM];   // transposed A tile
    __shared__ float Bs[BK][BN];

    const int tid = threadIdx.x;
    const int tx = tid & 15;         // 0..15 -> N
    const int ty = tid >> 4;         // 0..15 -> M
    const int bm = blockIdx.y * BM;
    const int bn = blockIdx.x * BN;

    // A-tile load mapping: 64 rows x 16 cols, one float4 per thread
    const int ar = tid >> 2;               // 0..63
    const int ac = (tid & 3) * 4;          // 0,4,8,12
    // B-tile load mapping: 16 rows x 64 cols, one float4 per thread
    const int br = tid >> 4;               // 0..15
    const int bc = (tid & 15) * 4;         // 0..60

    const float* Aptr = A + (size_t)(bm + ar) * K + ac;
    const float* Bptr = B + (size_t)br * N + bn + bc;

    float acc[4][4];
    #pragma unroll
    for (int i = 0; i < 4; i++)
        #pragma unroll
        for (int j = 0; j < 4; j++) acc[i][j] = 0.0f;

    for (int k0 = 0; k0 < K; k0 += BK) {
        float4 av = *reinterpret_cast<const float4*>(Aptr + k0);
        As[ac + 0][ar] = av.x;
        As[ac + 1][ar] = av.y;
        As[ac + 2][ar] = av.z;
        As[ac + 3][ar] = av.w;
        float4 bv = *reinterpret_cast<const float4*>(Bptr + (size_t)k0 * N);
        *reinterpret_cast<float4*>(&Bs[br][bc]) = bv;
        __syncthreads();

        #pragma unroll
        for (int kk = 0; kk < BK; kk++) {
            float4 a4 = *reinterpret_cast<const float4*>(&As[kk][ty * 4]);
            float4 b4 = *reinterpret_cast<const float4*>(&Bs[kk][tx * 4]);
            float a[4] = {a4.x, a4.y, a4.z, a4.w};
            float b[4] = {b4.x, b4.y, b4.z, b4.w};
            #pragma unroll
            for (int i = 0; i < 4; i++)
                #pragma unroll
                for (int j = 0; j < 4; j++)
                    acc[i][j] = fmaf(a[i], b[j], acc[i][j]);
        }
        __syncthreads();
    }

    #pragma unroll
    for (int i = 0; i < 4; i++) {
        const int row = bm + ty * 4 + i;
        float* Crow = C + (size_t)row * N + bn + tx * 4;
        #pragma unroll
        for (int j = 0; j < 4; j++) {
            float v = acc[i][j] + __ldg(&bias[bn + tx * 4 + j]);
            if (RELU) v = fmaxf(v, 0.0f);
            Crow[j] = v;
        }
    }
}

// ---------------------------------------------------------------------------
// Per-row min-max norm + uniform cubic B-spline + coeff dot + sp_bias
// One CTA (256 threads) per row of 1024 neurons.
// ---------------------------------------------------------------------------
__global__ __launch_bounds__(256)
void norm_spline_kernel(const float* __restrict__ h,
                        const float* __restrict__ coeff,   // [1024, 18]
                        const float* __restrict__ sp_bias, // [1024]
                        float* __restrict__ sp)
{
    const int row = blockIdx.x;
    const int tid = threadIdx.x;
    const float* hr = h + (size_t)row * D_HID;

    float4 v = reinterpret_cast<const float4*>(hr)[tid];
    float mn = fminf(fminf(v.x, v.y), fminf(v.z, v.w));
    float mx = fmaxf(fmaxf(v.x, v.y), fmaxf(v.z, v.w));

    #pragma unroll
    for (int o = 16; o > 0; o >>= 1) {
        mn = fminf(mn, __shfl_xor_sync(0xffffffffu, mn, o));
        mx = fmaxf(mx, __shfl_xor_sync(0xffffffffu, mx, o));
    }
    __shared__ float smn[8], smx[8];
    const int w = tid >> 5, l = tid & 31;
    if (l == 0) { smn[w] = mn; smx[w] = mx; }
    __syncthreads();
    mn = smn[0]; mx = smx[0];
    #pragma unroll
    for (int i = 1; i < 8; i++) {
        mn = fminf(mn, smn[i]);
        mx = fmaxf(mx, smx[i]);
    }

    const float scale = 15.0f / (mx - mn + 1e-8f);

    float xv[4] = {v.x, v.y, v.z, v.w};
    float out[4];
    #pragma unroll
    for (int j = 0; j < 4; j++) {
        const int n = tid * 4 + j;
        float xs = (xv[j] - mn) * scale;          // in [0, 15]
        int s = (int)xs;
        s = min(s, 14);
        if (s < 0) s = 0;
        const float u  = xs - (float)s;
        const float um = 1.0f - u;
        const float u2 = u * u;
        const float u3 = u2 * u;
        const float b0 = um * um * um * (1.0f / 6.0f);
        const float b1 = (3.0f * u3 - 6.0f * u2 + 4.0f) * (1.0f / 6.0f);
        const float b2 = (-3.0f * u3 + 3.0f * u2 + 3.0f * u + 1.0f) * (1.0f / 6.0f);
        const float b3 = u3 * (1.0f / 6.0f);
        const float* c = coeff + n * 18 + s;
        out[j] = fmaf(b0, __ldg(c + 0),
                 fmaf(b1, __ldg(c + 1),
                 fmaf(b2, __ldg(c + 2),
                      b3 * __ldg(c + 3)))) + __ldg(&sp_bias[n]);
    }
    reinterpret_cast<float4*>(sp + (size_t)row * D_HID)[tid] =
        make_float4(out[0], out[1], out[2], out[3]);
}

// ---------------------------------------------------------------------------
extern "C" void kernel_launch(void* const* d_in, const int* in_sizes, int n_in,
                              void* d_out, int out_size)
{
    const float* x       = (const float*)d_in[0];
    const float* W1      = (const float*)d_in[1];
    const float* b1      = (const float*)d_in[2];
    const float* coeff   = (const float*)d_in[3];
    const float* sp_bias = (const float*)d_in[4];
    const float* W2      = (const float*)d_in[5];
    const float* b2      = (const float*)d_in[6];
    float* out = (float*)d_out;

    float *h_ptr, *sp_ptr;
    cudaGetSymbolAddress((void**)&h_ptr,  g_h);
    cudaGetSymbolAddress((void**)&sp_ptr, g_sp);

    // GEMM1: h = x @ W1 + b1   (4096x1024, K=512)
    {
        dim3 grid(D_HID / 64, MROWS / 64);
        gemm_bias_kernel<false><<<grid, 256>>>(x, W1, b1, h_ptr, D_HID, D_IN);
    }
    // norm + spline: sp = spline(norm(h)) . coeff + sp_bias
    norm_spline_kernel<<<MROWS, 256>>>(h_ptr, coeff, sp_bias, sp_ptr);
    // GEMM2: out = relu(sp @ W2 + b2)  (4096x512, K=1024)
    {
        dim3 grid(D_OUT / 64, MROWS / 64);
        gemm_bias_kernel<true><<<grid, 256>>>(sp_ptr, W2, b2, out, D_OUT, D_HID);
    }
}

// round 10
// speedup vs baseline: 1.9481x; 1.9481x over previous
#include <cuda_runtime.h>
#include <cuda_bf16.h>
#include <cstdint>

#define MROWS 4096
#define D_IN  512
#define D_HID 1024
#define D_OUT 512

#define KP1 (3*D_IN)     // 1536 augmented K for GEMM1
#define KP2 (3*D_HID)    // 3072 augmented K for GEMM2

// ---------------- scratch (no cudaMalloc allowed) ----------------
__device__ __nv_bfloat16 g_a1[(size_t)MROWS * KP1];  // A1' [r][k'] segs: hi|lo|hi
__device__ __nv_bfloat16 g_b1[(size_t)D_HID * KP1];  // B1' [n][k'] segs: hi|hi|lo
__device__ float         g_h [(size_t)MROWS * D_HID];
__device__ __nv_bfloat16 g_a2[(size_t)MROWS * KP2];  // A2' [r][k'] segs: hi|lo|hi
__device__ __nv_bfloat16 g_b2[(size_t)D_OUT * KP2];  // B2' [n][k'] segs: hi|hi|lo

// ---------------- helpers ----------------
__device__ __forceinline__ uint32_t smem_u32(const void* p) {
    uint32_t a;
    asm("{ .reg .u64 t; cvta.to.shared.u64 t, %1; cvt.u32.u64 %0, t; }" : "=r"(a) : "l"(p));
    return a;
}
__device__ __forceinline__ void cp_async16(uint32_t dst, const void* src) {
    asm volatile("cp.async.cg.shared.global [%0], [%1], 16;" :: "r"(dst), "l"(src));
}
#define CP_COMMIT() asm volatile("cp.async.commit_group;" ::: "memory")
#define CP_WAIT(n)  asm volatile("cp.async.wait_group %0;" :: "n"(n) : "memory")

__device__ __forceinline__ void ldsm_x4(uint32_t& r0, uint32_t& r1, uint32_t& r2, uint32_t& r3,
                                        uint32_t addr) {
    asm volatile("ldmatrix.sync.aligned.m8n8.x4.shared.b16 {%0,%1,%2,%3}, [%4];"
                 : "=r"(r0), "=r"(r1), "=r"(r2), "=r"(r3) : "r"(addr));
}
__device__ __forceinline__ void mma16816(float* c, uint32_t a0, uint32_t a1, uint32_t a2,
                                         uint32_t a3, uint32_t b0, uint32_t b1) {
    asm volatile(
        "mma.sync.aligned.m16n8k16.row.col.f32.bf16.bf16.f32 "
        "{%0,%1,%2,%3}, {%4,%5,%6,%7}, {%8,%9}, {%0,%1,%2,%3};"
        : "+f"(c[0]), "+f"(c[1]), "+f"(c[2]), "+f"(c[3])
        : "r"(a0), "r"(a1), "r"(a2), "r"(a3), "r"(b0), "r"(b1));
}

__device__ __forceinline__ uint32_t pack2(__nv_bfloat16 a, __nv_bfloat16 b) {
    __nv_bfloat162 t; t.x = a; t.y = b;
    return *reinterpret_cast<uint32_t*>(&t);
}
__device__ __forceinline__ void split_bf16(float x, __nv_bfloat16& hi, __nv_bfloat16& lo) {
    hi = __float2bfloat16(x);
    lo = __float2bfloat16(x - __bfloat162float(hi));
}

// ---------------------------------------------------------------------------
// Pack x [4096,512] fp32 -> A1' [4096][1536] bf16 row-major, segs hi|lo|hi
// ---------------------------------------------------------------------------
__global__ __launch_bounds__(256)
void pack_x_kernel(const float* __restrict__ X, __nv_bfloat16* __restrict__ out)
{
    int idx = blockIdx.x * blockDim.x + threadIdx.x;      // MROWS * KP1/4 threads
    int r   = idx / (KP1 / 4);
    int kp  = (idx - r * (KP1 / 4)) * 4;
    int seg = kp / D_IN;
    int k   = kp - seg * D_IN;
    float4 v = *reinterpret_cast<const float4*>(X + (size_t)r * D_IN + k);
    __nv_bfloat16 h0, l0, h1, l1, h2, l2, h3, l3;
    split_bf16(v.x, h0, l0); split_bf16(v.y, h1, l1);
    split_bf16(v.z, h2, l2); split_bf16(v.w, h3, l3);
    uint2 w;
    if (seg == 1) { w.x = pack2(l0, l1); w.y = pack2(l2, l3); }
    else          { w.x = pack2(h0, h1); w.y = pack2(h2, h3); }
    *reinterpret_cast<uint2*>(out + (size_t)r * KP1 + kp) = w;
}

// ---------------------------------------------------------------------------
// Pack W [K,N] fp32 -> B' [N][3K] bf16 row-major, segs hi|hi|lo
// ---------------------------------------------------------------------------
__global__ __launch_bounds__(256)
void pack_w_kernel(const float* __restrict__ W, __nv_bfloat16* __restrict__ out,
                   int K, int N)
{
    int idx = blockIdx.x * blockDim.x + threadIdx.x;      // N * (K/4) threads
    int kq4 = K >> 2;
    int n   = idx / kq4;
    int k   = (idx - n * kq4) * 4;
    __nv_bfloat16 h[4], l[4];
    #pragma unroll
    for (int i = 0; i < 4; i++)
        split_bf16(W[(size_t)(k + i) * N + n], h[i], l[i]);
    uint2 whi, wlo;
    whi.x = pack2(h[0], h[1]); whi.y = pack2(h[2], h[3]);
    wlo.x = pack2(l[0], l[1]); wlo.y = pack2(l[2], l[3]);
    __nv_bfloat16* base = out + (size_t)n * (3 * K);
    *reinterpret_cast<uint2*>(base + k)         = whi;   // seg0 hi
    *reinterpret_cast<uint2*>(base + K + k)     = whi;   // seg1 hi
    *reinterpret_cast<uint2*>(base + 2 * K + k) = wlo;   // seg2 lo
}

// ---------------------------------------------------------------------------
// norm + cubic B-spline + coeff dot + sp_bias, emit packed A2' (hi|lo|hi)
// One CTA (256 threads) per row of 1024 neurons.
// ---------------------------------------------------------------------------
__global__ __launch_bounds__(256)
void norm_spline_pack_kernel(const float* __restrict__ h,
                             const float* __restrict__ coeff,   // [1024, 18]
                             const float* __restrict__ sp_bias, // [1024]
                             __nv_bfloat16* __restrict__ out)   // A2'
{
    const int row = blockIdx.x;
    const int tid = threadIdx.x;
    const float* hr = h + (size_t)row * D_HID;

    float4 v = reinterpret_cast<const float4*>(hr)[tid];
    float mn = fminf(fminf(v.x, v.y), fminf(v.z, v.w));
    float mx = fmaxf(fmaxf(v.x, v.y), fmaxf(v.z, v.w));
    #pragma unroll
    for (int o = 16; o > 0; o >>= 1) {
        mn = fminf(mn, __shfl_xor_sync(0xffffffffu, mn, o));
        mx = fmaxf(mx, __shfl_xor_sync(0xffffffffu, mx, o));
    }
    __shared__ float smn[8], smx[8];
    const int w = tid >> 5, l = tid & 31;
    if (l == 0) { smn[w] = mn; smx[w] = mx; }
    __syncthreads();
    mn = smn[0]; mx = smx[0];
    #pragma unroll
    for (int i = 1; i < 8; i++) { mn = fminf(mn, smn[i]); mx = fmaxf(mx, smx[i]); }

    const float scale = 15.0f / (mx - mn + 1e-8f);
    float xv[4] = {v.x, v.y, v.z, v.w};
    __nv_bfloat16 hi[4], lo[4];
    #pragma unroll
    for (int j = 0; j < 4; j++) {
        const int n = tid * 4 + j;
        float xs = (xv[j] - mn) * scale;
        int s = (int)xs;
        s = min(s, 14);
        if (s < 0) s = 0;
        const float u  = xs - (float)s;
        const float um = 1.0f - u;
        const float u2 = u * u;
        const float u3 = u2 * u;
        const float b0 = um * um * um * (1.0f / 6.0f);
        const float b1 = (3.0f * u3 - 6.0f * u2 + 4.0f) * (1.0f / 6.0f);
        const float b2 = (-3.0f * u3 + 3.0f * u2 + 3.0f * u + 1.0f) * (1.0f / 6.0f);
        const float b3 = u3 * (1.0f / 6.0f);
        const float* c = coeff + n * 18 + s;
        float sp = fmaf(b0, __ldg(c + 0),
                   fmaf(b1, __ldg(c + 1),
                   fmaf(b2, __ldg(c + 2),
                        b3 * __ldg(c + 3)))) + __ldg(&sp_bias[n]);
        split_bf16(sp, hi[j], lo[j]);
    }
    uint2 whi, wlo;
    whi.x = pack2(hi[0], hi[1]); whi.y = pack2(hi[2], hi[3]);
    wlo.x = pack2(lo[0], lo[1]); wlo.y = pack2(lo[2], lo[3]);
    const int n0 = tid * 4;
    __nv_bfloat16* base = out + (size_t)row * KP2;
    *reinterpret_cast<uint2*>(base + n0)             = whi;  // seg0 hi
    *reinterpret_cast<uint2*>(base + D_HID + n0)     = wlo;  // seg1 lo
    *reinterpret_cast<uint2*>(base + 2 * D_HID + n0) = whi;  // seg2 hi
}

// ---------------------------------------------------------------------------
// bf16 mma.sync GEMM: C[128 x 64] per CTA = A'[128][K'] . B'[64][K']^T + bias
// 256 threads = 8 warps (4 M x 2 N), BK=64, double-buffered cp.async.
// SMEM rows padded to 144B (72 halves) for conflict-free ldmatrix.
// ---------------------------------------------------------------------------
template<int NK, bool RELU>
__global__ void __launch_bounds__(256, 2)
gemm_mma(const __nv_bfloat16* __restrict__ Apk,
         const __nv_bfloat16* __restrict__ Bpk,
         const float* __restrict__ bias,
         float* __restrict__ C, int ldc)
{
    constexpr int KPB = NK * 128;            // bytes per A/B row (K' * 2)
    constexpr int ROWB = 144;                // padded smem row bytes
    constexpr int ASTG = 128 * ROWB;         // 18432
    constexpr int BSTG = 64 * ROWB;          // 9216
    constexpr int STG  = ASTG + BSTG;        // 27648

    extern __shared__ char smem[];
    const uint32_t sb = smem_u32(smem);

    const int tid  = threadIdx.x;
    const int wid  = tid >> 5;
    const int lane = tid & 31;
    const int wm   = wid & 3;                // 0..3 -> M
    const int wn   = wid >> 2;               // 0..1 -> N

    const char* Ag = (const char*)Apk + (size_t)(blockIdx.y * 128) * KPB;
    const char* Bg = (const char*)Bpk + (size_t)(blockIdx.x * 64) * KPB;

    auto load_stage = [&](int kb, int s) {
        const uint32_t as = sb + s * STG;
        const uint32_t bs = as + ASTG;
        const int koff = kb * 128;           // byte offset along K'
        #pragma unroll
        for (int i = 0; i < 4; i++) {        // A: 1024 chunks of 16B
            int idx = i * 256 + tid;
            int row = idx >> 3, ch = idx & 7;
            cp_async16(as + row * ROWB + ch * 16,
                       Ag + (size_t)row * KPB + koff + ch * 16);
        }
        #pragma unroll
        for (int i = 0; i < 2; i++) {        // B: 512 chunks of 16B
            int idx = i * 256 + tid;
            int row = idx >> 3, ch = idx & 7;
            cp_async16(bs + row * ROWB + ch * 16,
                       Bg + (size_t)row * KPB + koff + ch * 16);
        }
    };

    float acc[2][4][4];
    #pragma unroll
    for (int i = 0; i < 2; i++)
        #pragma unroll
        for (int j = 0; j < 4; j++)
            #pragma unroll
            for (int t = 0; t < 4; t++) acc[i][j][t] = 0.0f;

    load_stage(0, 0);
    CP_COMMIT();

    // ldmatrix per-lane address components
    const int a_lrow = lane & 15;
    const int a_lcb  = (lane >> 4) * 16;     // byte offset for k half-block
    const int b_sub  = lane >> 3;
    const int b_noff = ((b_sub >> 1) << 3) + (lane & 7);
    const int b_kb   = (b_sub & 1) * 16;

    for (int kb = 0; kb < NK; kb++) {
        const int s = kb & 1;
        if (kb + 1 < NK) {
            load_stage(kb + 1, s ^ 1);
            CP_COMMIT();
            CP_WAIT(1);
        } else {
            CP_WAIT(0);
        }
        __syncthreads();

        const uint32_t as = sb + s * STG;
        const uint32_t bs = as + ASTG;

        #pragma unroll
        for (int k0 = 0; k0 < 64; k0 += 16) {
            uint32_t a[2][4];
            #pragma unroll
            for (int mt = 0; mt < 2; mt++) {
                uint32_t addr = as + (wm * 32 + mt * 16 + a_lrow) * ROWB + k0 * 2 + a_lcb;
                ldsm_x4(a[mt][0], a[mt][1], a[mt][2], a[mt][3], addr);
            }
            // B: non-trans ldmatrix of [n][k] rows gives the required col-major
            // fragment directly (two k-adjacent bf16 at fixed n per register).
            uint32_t b[4][2];
            #pragma unroll
            for (int p = 0; p < 2; p++) {
                uint32_t addr = bs + (wn * 32 + p * 16 + b_noff) * ROWB + k0 * 2 + b_kb;
                ldsm_x4(b[p * 2][0], b[p * 2][1], b[p * 2 + 1][0], b[p * 2 + 1][1], addr);
            }
            #pragma unroll
            for (int mt = 0; mt < 2; mt++)
                #pragma unroll
                for (int nt = 0; nt < 4; nt++)
                    mma16816(acc[mt][nt], a[mt][0], a[mt][1], a[mt][2], a[mt][3],
                             b[nt][0], b[nt][1]);
        }
        __syncthreads();
    }

    // epilogue: bias (+ optional ReLU), direct global stores
    const int g  = lane >> 2;
    const int tg = lane & 3;
    #pragma unroll
    for (int mt = 0; mt < 2; mt++) {
        const int row0 = blockIdx.y * 128 + wm * 32 + mt * 16 + g;
        #pragma unroll
        for (int nt = 0; nt < 4; nt++) {
            const int col = blockIdx.x * 64 + wn * 32 + nt * 8 + tg * 2;
            float2 bv = *reinterpret_cast<const float2*>(bias + col);
            float2 o0, o1;
            o0.x = acc[mt][nt][0] + bv.x; o0.y = acc[mt][nt][1] + bv.y;
            o1.x = acc[mt][nt][2] + bv.x; o1.y = acc[mt][nt][3] + bv.y;
            if (RELU) {
                o0.x = fmaxf(o0.x, 0.0f); o0.y = fmaxf(o0.y, 0.0f);
                o1.x = fmaxf(o1.x, 0.0f); o1.y = fmaxf(o1.y, 0.0f);
            }
            *reinterpret_cast<float2*>(C + (size_t)row0 * ldc + col)       = o0;
            *reinterpret_cast<float2*>(C + (size_t)(row0 + 8) * ldc + col) = o1;
        }
    }
}

// ---------------------------------------------------------------------------
extern "C" void kernel_launch(void* const* d_in, const int* in_sizes, int n_in,
                              void* d_out, int out_size)
{
    const float* x       = (const float*)d_in[0];
    const float* W1      = (const float*)d_in[1];
    const float* b1      = (const float*)d_in[2];
    const float* coeff   = (const float*)d_in[3];
    const float* sp_bias = (const float*)d_in[4];
    const float* W2      = (const float*)d_in[5];
    const float* b2      = (const float*)d_in[6];
    float* out = (float*)d_out;

    __nv_bfloat16 *a1, *bp1, *a2, *bp2;
    float* h_ptr;
    cudaGetSymbolAddress((void**)&a1,    g_a1);
    cudaGetSymbolAddress((void**)&bp1,   g_b1);
    cudaGetSymbolAddress((void**)&h_ptr, g_h);
    cudaGetSymbolAddress((void**)&a2,    g_a2);
    cudaGetSymbolAddress((void**)&bp2,   g_b2);

    constexpr int SMEM = 2 * (128 * 144 + 64 * 144);  // 55296 bytes
    cudaFuncSetAttribute(gemm_mma<KP1 / 64, false>,
                         cudaFuncAttributeMaxDynamicSharedMemorySize, SMEM);
    cudaFuncSetAttribute(gemm_mma<KP2 / 64, true>,
                         cudaFuncAttributeMaxDynamicSharedMemorySize, SMEM);

    // pack inputs
    pack_x_kernel<<<(MROWS * (KP1 / 4)) / 256, 256>>>(x, a1);
    pack_w_kernel<<<(D_HID * (D_IN / 4)) / 256, 256>>>(W1, bp1, D_IN, D_HID);
    pack_w_kernel<<<(D_OUT * (D_HID / 4)) / 256, 256>>>(W2, bp2, D_HID, D_OUT);

    // GEMM1: h = x @ W1 + b1   (M=4096, N=1024, K'=1536)
    {
        dim3 grid(D_HID / 64, MROWS / 128);
        gemm_mma<KP1 / 64, false><<<grid, 256, SMEM>>>(a1, bp1, b1, h_ptr, D_HID);
    }
    // norm + spline + pack A2'
    norm_spline_pack_kernel<<<MROWS, 256>>>(h_ptr, coeff, sp_bias, a2);
    // GEMM2: out = relu(sp @ W2 + b2)  (M=4096, N=512, K'=3072)
    {
        dim3 grid(D_OUT / 64, MROWS / 128);
        gemm_mma<KP2 / 64, true><<<grid, 256, SMEM>>>(a2, bp2, b2, out, D_OUT);
    }
}

// round 13
// speedup vs baseline: 2.1723x; 1.1151x over previous
#include <cuda_runtime.h>
#include <cuda_bf16.h>
#include <cstdint>

#define MROWS 4096
#define D_IN  512
#define D_HID 1024
#define D_OUT 512

#define KP1 (3*D_IN)     // 1536 augmented K for GEMM1
#define KP2 (3*D_HID)    // 3072 augmented K for GEMM2

// ---------------- scratch (no cudaMalloc allowed) ----------------
__device__ __nv_bfloat16 g_a1[(size_t)MROWS * KP1];  // A1' [r][k'] segs: hi|lo|hi
__device__ __nv_bfloat16 g_b1[(size_t)D_HID * KP1];  // B1' [n][k'] segs: hi|hi|lo
__device__ float         g_h [(size_t)MROWS * D_HID];
__device__ __nv_bfloat16 g_a2[(size_t)MROWS * KP2];  // A2' [r][k'] segs: hi|lo|hi
__device__ __nv_bfloat16 g_b2[(size_t)D_OUT * KP2];  // B2' [n][k'] segs: hi|hi|lo

// ---------------- helpers ----------------
__device__ __forceinline__ uint32_t smem_u32(const void* p) {
    uint32_t a;
    asm("{ .reg .u64 t; cvta.to.shared.u64 t, %1; cvt.u32.u64 %0, t; }" : "=r"(a) : "l"(p));
    return a;
}
__device__ __forceinline__ void cp_async16(uint32_t dst, const void* src) {
    asm volatile("cp.async.cg.shared.global [%0], [%1], 16;" :: "r"(dst), "l"(src));
}
#define CP_COMMIT() asm volatile("cp.async.commit_group;" ::: "memory")
#define CP_WAIT(n)  asm volatile("cp.async.wait_group %0;" :: "n"(n) : "memory")

__device__ __forceinline__ void ldsm_x4(uint32_t& r0, uint32_t& r1, uint32_t& r2, uint32_t& r3,
                                        uint32_t addr) {
    asm volatile("ldmatrix.sync.aligned.m8n8.x4.shared.b16 {%0,%1,%2,%3}, [%4];"
                 : "=r"(r0), "=r"(r1), "=r"(r2), "=r"(r3) : "r"(addr));
}
__device__ __forceinline__ void mma16816(float* c, uint32_t a0, uint32_t a1, uint32_t a2,
                                         uint32_t a3, uint32_t b0, uint32_t b1) {
    asm volatile(
        "mma.sync.aligned.m16n8k16.row.col.f32.bf16.bf16.f32 "
        "{%0,%1,%2,%3}, {%4,%5,%6,%7}, {%8,%9}, {%0,%1,%2,%3};"
        : "+f"(c[0]), "+f"(c[1]), "+f"(c[2]), "+f"(c[3])
        : "r"(a0), "r"(a1), "r"(a2), "r"(a3), "r"(b0), "r"(b1));
}

__device__ __forceinline__ uint32_t pack2(__nv_bfloat16 a, __nv_bfloat16 b) {
    __nv_bfloat162 t; t.x = a; t.y = b;
    return *reinterpret_cast<uint32_t*>(&t);
}
__device__ __forceinline__ void split_bf16(float x, __nv_bfloat16& hi, __nv_bfloat16& lo) {
    hi = __float2bfloat16(x);
    lo = __float2bfloat16(x - __bfloat162float(hi));
}

// ---------------------------------------------------------------------------
// Pack x [4096,512] fp32 -> A1' [4096][1536] bf16 row-major, segs hi|lo|hi
// ---------------------------------------------------------------------------
__global__ __launch_bounds__(256)
void pack_x_kernel(const float* __restrict__ X, __nv_bfloat16* __restrict__ out)
{
    int idx = blockIdx.x * blockDim.x + threadIdx.x;      // MROWS * KP1/4 threads
    int r   = idx / (KP1 / 4);
    int kp  = (idx - r * (KP1 / 4)) * 4;
    int seg = kp / D_IN;
    int k   = kp - seg * D_IN;
    float4 v = *reinterpret_cast<const float4*>(X + (size_t)r * D_IN + k);
    __nv_bfloat16 h0, l0, h1, l1, h2, l2, h3, l3;
    split_bf16(v.x, h0, l0); split_bf16(v.y, h1, l1);
    split_bf16(v.z, h2, l2); split_bf16(v.w, h3, l3);
    uint2 w;
    if (seg == 1) { w.x = pack2(l0, l1); w.y = pack2(l2, l3); }
    else          { w.x = pack2(h0, h1); w.y = pack2(h2, h3); }
    *reinterpret_cast<uint2*>(out + (size_t)r * KP1 + kp) = w;
}

// ---------------------------------------------------------------------------
// Pack W [K,N] fp32 -> B' [N][3K] bf16 row-major, segs hi|hi|lo
// ---------------------------------------------------------------------------
__global__ __launch_bounds__(256)
void pack_w_kernel(const float* __restrict__ W, __nv_bfloat16* __restrict__ out,
                   int K, int N)
{
    int idx = blockIdx.x * blockDim.x + threadIdx.x;      // N * (K/4) threads
    int kq4 = K >> 2;
    int n   = idx / kq4;
    int k   = (idx - n * kq4) * 4;
    __nv_bfloat16 h[4], l[4];
    #pragma unroll
    for (int i = 0; i < 4; i++)
        split_bf16(W[(size_t)(k + i) * N + n], h[i], l[i]);
    uint2 whi, wlo;
    whi.x = pack2(h[0], h[1]); whi.y = pack2(h[2], h[3]);
    wlo.x = pack2(l[0], l[1]); wlo.y = pack2(l[2], l[3]);
    __nv_bfloat16* base = out + (size_t)n * (3 * K);
    *reinterpret_cast<uint2*>(base + k)         = whi;   // seg0 hi
    *reinterpret_cast<uint2*>(base + K + k)     = whi;   // seg1 hi
    *reinterpret_cast<uint2*>(base + 2 * K + k) = wlo;   // seg2 lo
}

// ---------------------------------------------------------------------------
// norm + cubic B-spline + coeff dot + sp_bias, emit packed A2' (hi|lo|hi)
// One CTA (256 threads) per row of 1024 neurons.
// ---------------------------------------------------------------------------
__global__ __launch_bounds__(256)
void norm_spline_pack_kernel(const float* __restrict__ h,
                             const float* __restrict__ coeff,   // [1024, 18]
                             const float* __restrict__ sp_bias, // [1024]
                             __nv_bfloat16* __restrict__ out)   // A2'
{
    const int row = blockIdx.x;
    const int tid = threadIdx.x;
    const float* hr = h + (size_t)row * D_HID;

    float4 v = reinterpret_cast<const float4*>(hr)[tid];
    float mn = fminf(fminf(v.x, v.y), fminf(v.z, v.w));
    float mx = fmaxf(fmaxf(v.x, v.y), fmaxf(v.z, v.w));
    #pragma unroll
    for (int o = 16; o > 0; o >>= 1) {
        mn = fminf(mn, __shfl_xor_sync(0xffffffffu, mn, o));
        mx = fmaxf(mx, __shfl_xor_sync(0xffffffffu, mx, o));
    }
    __shared__ float smn[8], smx[8];
    const int w = tid >> 5, l = tid & 31;
    if (l == 0) { smn[w] = mn; smx[w] = mx; }
    __syncthreads();
    mn = smn[0]; mx = smx[0];
    #pragma unroll
    for (int i = 1; i < 8; i++) { mn = fminf(mn, smn[i]); mx = fmaxf(mx, smx[i]); }

    const float scale = 15.0f / (mx - mn + 1e-8f);
    float xv[4] = {v.x, v.y, v.z, v.w};
    __nv_bfloat16 hi[4], lo[4];
    #pragma unroll
    for (int j = 0; j < 4; j++) {
        const int n = tid * 4 + j;
        float xs = (xv[j] - mn) * scale;
        int s = (int)xs;
        s = min(s, 14);
        if (s < 0) s = 0;
        const float u  = xs - (float)s;
        const float um = 1.0f - u;
        const float u2 = u * u;
        const float u3 = u2 * u;
        const float b0 = um * um * um * (1.0f / 6.0f);
        const float b1 = (3.0f * u3 - 6.0f * u2 + 4.0f) * (1.0f / 6.0f);
        const float b2 = (-3.0f * u3 + 3.0f * u2 + 3.0f * u + 1.0f) * (1.0f / 6.0f);
        const float b3 = u3 * (1.0f / 6.0f);
        const float* c = coeff + n * 18 + s;
        float sp = fmaf(b0, __ldg(c + 0),
                   fmaf(b1, __ldg(c + 1),
                   fmaf(b2, __ldg(c + 2),
                        b3 * __ldg(c + 3)))) + __ldg(&sp_bias[n]);
        split_bf16(sp, hi[j], lo[j]);
    }
    uint2 whi, wlo;
    whi.x = pack2(hi[0], hi[1]); whi.y = pack2(hi[2], hi[3]);
    wlo.x = pack2(lo[0], lo[1]); wlo.y = pack2(lo[2], lo[3]);
    const int n0 = tid * 4;
    __nv_bfloat16* base = out + (size_t)row * KP2;
    *reinterpret_cast<uint2*>(base + n0)             = whi;  // seg0 hi
    *reinterpret_cast<uint2*>(base + D_HID + n0)     = wlo;  // seg1 lo
    *reinterpret_cast<uint2*>(base + 2 * D_HID + n0) = whi;  // seg2 hi
}

// ---------------------------------------------------------------------------
// bf16 mma.sync GEMM: C[128 x BN] per CTA = A'[128][K'] . B'[BN][K']^T + bias
// 256 threads = 8 warps (4 M x 2 N), warp tile 32 x (BN/2), BK=64.
// 3-stage cp.async ring, ONE __syncthreads per BK iteration.
// SMEM rows padded to 144B for conflict-free ldmatrix.
// ---------------------------------------------------------------------------
template<int NK, int BN, bool RELU>
__global__ void __launch_bounds__(256, 2)
gemm_mma(const __nv_bfloat16* __restrict__ Apk,
         const __nv_bfloat16* __restrict__ Bpk,
         const float* __restrict__ bias,
         float* __restrict__ C, int ldc)
{
    constexpr int KPB  = NK * 128;           // bytes per A/B row (K' * 2)
    constexpr int ROWB = 144;                // padded smem row bytes
    constexpr int ASTG = 128 * ROWB;
    constexpr int BSTG = BN * ROWB;
    constexpr int STG  = ASTG + BSTG;
    constexpr int NT   = BN / 16;            // per-warp n sub-blocks (8 or 4)

    extern __shared__ char smem[];
    const uint32_t sb = smem_u32(smem);

    const int tid  = threadIdx.x;
    const int wid  = tid >> 5;
    const int lane = tid & 31;
    const int wm   = wid & 3;                // 0..3 -> M (32 rows each)
    const int wn   = wid >> 2;               // 0..1 -> N (BN/2 cols each)

    const char* Ag = (const char*)Apk + (size_t)(blockIdx.y * 128) * KPB;
    const char* Bg = (const char*)Bpk + (size_t)(blockIdx.x * BN) * KPB;

    auto load_stage = [&](int kb, int s) {
        const uint32_t as = sb + s * STG;
        const uint32_t bs = as + ASTG;
        const int koff = kb * 128;           // byte offset along K'
        #pragma unroll
        for (int i = 0; i < 4; i++) {        // A: 1024 chunks of 16B
            int idx = i * 256 + tid;
            int row = idx >> 3, ch = idx & 7;
            cp_async16(as + row * ROWB + ch * 16,
                       Ag + (size_t)row * KPB + koff + ch * 16);
        }
        #pragma unroll
        for (int i = 0; i < BN / 32; i++) {  // B: BN*8 chunks of 16B
            int idx = i * 256 + tid;
            int row = idx >> 3, ch = idx & 7;
            cp_async16(bs + row * ROWB + ch * 16,
                       Bg + (size_t)row * KPB + koff + ch * 16);
        }
    };

    float acc[2][NT][4];
    #pragma unroll
    for (int i = 0; i < 2; i++)
        #pragma unroll
        for (int j = 0; j < NT; j++)
            #pragma unroll
            for (int t = 0; t < 4; t++) acc[i][j][t] = 0.0f;

    load_stage(0, 0);
    CP_COMMIT();
    load_stage(1, 1);
    CP_COMMIT();

    // ldmatrix per-lane address components
    const int a_lrow = lane & 15;
    const int a_lcb  = (lane >> 4) * 16;     // byte offset for k half-block
    const int b_sub  = lane >> 3;
    const int b_noff = ((b_sub >> 1) << 3) + (lane & 7);
    const int b_kb   = (b_sub & 1) * 16;

    for (int kb = 0; kb < NK; kb++) {
        if (kb + 1 < NK) { CP_WAIT(1); } else { CP_WAIT(0); }
        __syncthreads();                      // stage kb ready; prev compute done

        const int s = kb % 3;
        const uint32_t as = sb + s * STG;
        const uint32_t bs = as + ASTG;

        // issue next-next stage load immediately (targets buffer consumed at kb-1)
        if (kb + 2 < NK) {
            load_stage(kb + 2, (kb + 2) % 3);
            CP_COMMIT();
        }

        #pragma unroll
        for (int k0 = 0; k0 < 64; k0 += 16) {
            uint32_t a[2][4];
            #pragma unroll
            for (int mt = 0; mt < 2; mt++) {
                uint32_t addr = as + (wm * 32 + mt * 16 + a_lrow) * ROWB + k0 * 2 + a_lcb;
                ldsm_x4(a[mt][0], a[mt][1], a[mt][2], a[mt][3], addr);
            }
            // B: non-trans ldmatrix of [n][k] rows gives the required col-major
            // fragment directly (two k-adjacent bf16 at fixed n per register).
            uint32_t b[NT][2];
            #pragma unroll
            for (int p = 0; p < NT / 2; p++) {
                uint32_t addr = bs + (wn * (8 * NT) + p * 16 + b_noff) * ROWB + k0 * 2 + b_kb;
                ldsm_x4(b[p * 2][0], b[p * 2][1], b[p * 2 + 1][0], b[p * 2 + 1][1], addr);
            }
            #pragma unroll
            for (int mt = 0; mt < 2; mt++)
                #pragma unroll
                for (int nt = 0; nt < NT; nt++)
                    mma16816(acc[mt][nt], a[mt][0], a[mt][1], a[mt][2], a[mt][3],
                             b[nt][0], b[nt][1]);
        }
    }

    // epilogue: bias (+ optional ReLU), direct global stores
    const int g  = lane >> 2;
    const int tg = lane & 3;
    #pragma unroll
    for (int mt = 0; mt < 2; mt++) {
        const int row0 = blockIdx.y * 128 + wm * 32 + mt * 16 + g;
        #pragma unroll
        for (int nt = 0; nt < NT; nt++) {
            const int col = blockIdx.x * BN + wn * (8 * NT) + nt * 8 + tg * 2;
            float2 bv = *reinterpret_cast<const float2*>(bias + col);
            float2 o0, o1;
            o0.x = acc[mt][nt][0] + bv.x; o0.y = acc[mt][nt][1] + bv.y;
            o1.x = acc[mt][nt][2] + bv.x; o1.y = acc[mt][nt][3] + bv.y;
            if (RELU) {
                o0.x = fmaxf(o0.x, 0.0f); o0.y = fmaxf(o0.y, 0.0f);
                o1.x = fmaxf(o1.x, 0.0f); o1.y = fmaxf(o1.y, 0.0f);
            }
            *reinterpret_cast<float2*>(C + (size_t)row0 * ldc + col)       = o0;
            *reinterpret_cast<float2*>(C + (size_t)(row0 + 8) * ldc + col) = o1;
        }
    }
}

// ---------------------------------------------------------------------------
extern "C" void kernel_launch(void* const* d_in, const int* in_sizes, int n_in,
                              void* d_out, int out_size)
{
    const float* x       = (const float*)d_in[0];
    const float* W1      = (const float*)d_in[1];
    const float* b1      = (const float*)d_in[2];
    const float* coeff   = (const float*)d_in[3];
    const float* sp_bias = (const float*)d_in[4];
    const float* W2      = (const float*)d_in[5];
    const float* b2      = (const float*)d_in[6];
    float* out = (float*)d_out;

    __nv_bfloat16 *a1, *bp1, *a2, *bp2;
    float* h_ptr;
    cudaGetSymbolAddress((void**)&a1,    g_a1);
    cudaGetSymbolAddress((void**)&bp1,   g_b1);
    cudaGetSymbolAddress((void**)&h_ptr, g_h);
    cudaGetSymbolAddress((void**)&a2,    g_a2);
    cudaGetSymbolAddress((void**)&bp2,   g_b2);

    constexpr int SMEM1 = 3 * (128 * 144 + 128 * 144);  // 110592 (BN=128)
    constexpr int SMEM2 = 3 * (128 * 144 + 64 * 144);   // 82944  (BN=64)
    cudaFuncSetAttribute(gemm_mma<KP1 / 64, 128, false>,
                         cudaFuncAttributeMaxDynamicSharedMemorySize, SMEM1);
    cudaFuncSetAttribute(gemm_mma<KP2 / 64, 64, true>,
                         cudaFuncAttributeMaxDynamicSharedMemorySize, SMEM2);

    // pack inputs
    pack_x_kernel<<<(MROWS * (KP1 / 4)) / 256, 256>>>(x, a1);
    pack_w_kernel<<<(D_HID * (D_IN / 4)) / 256, 256>>>(W1, bp1, D_IN, D_HID);
    pack_w_kernel<<<(D_OUT * (D_HID / 4)) / 256, 256>>>(W2, bp2, D_HID, D_OUT);

    // GEMM1: h = x @ W1 + b1   (M=4096, N=1024, K'=1536)
    {
        dim3 grid(D_HID / 128, MROWS / 128);
        gemm_mma<KP1 / 64, 128, false><<<grid, 256, SMEM1>>>(a1, bp1, b1, h_ptr, D_HID);
    }
    // norm + spline + pack A2'
    norm_spline_pack_kernel<<<MROWS, 256>>>(h_ptr, coeff, sp_bias, a2);
    // GEMM2: out = relu(sp @ W2 + b2)  (M=4096, N=512, K'=3072)
    {
        dim3 grid(D_OUT / 64, MROWS / 128);
        gemm_mma<KP2 / 64, 64, true><<<grid, 256, SMEM2>>>(a2, bp2, b2, out, D_OUT);
    }
}

// round 17
// speedup vs baseline: 2.1847x; 1.0057x over previous
#include <cuda_runtime.h>
#include <cuda_bf16.h>
#include <cstdint>

#define MROWS 4096
#define D_IN  512
#define D_HID 1024
#define D_OUT 512

// Dedup storage: [hi|lo] only (K's = 2K). GEMM expands to 3 cross terms via
// per-kb offset remap, so augmented K' = 3K is unchanged at the MMA level.
#define KS1 (2*D_IN)     // 1024 stored K for GEMM1 operands
#define KS2 (2*D_HID)    // 2048 stored K for GEMM2 operands
#define NK1 ((3*D_IN)/64)    // 24 MMA k-blocks
#define NK2 ((3*D_HID)/64)   // 48

// ---------------- scratch (no cudaMalloc allowed) ----------------
__device__ __nv_bfloat16 g_a1[(size_t)MROWS * KS1];  // x  packed [r][hi|lo]
__device__ __nv_bfloat16 g_b1[(size_t)D_HID * KS1];  // W1 packed [n][hi|lo]
__device__ float         g_h [(size_t)MROWS * D_HID];
__device__ __nv_bfloat16 g_a2[(size_t)MROWS * KS2];  // sp packed [r][hi|lo]
__device__ __nv_bfloat16 g_b2[(size_t)D_OUT * KS2];  // W2 packed [n][hi|lo]

// ---------------- helpers ----------------
__device__ __forceinline__ uint32_t smem_u32(const void* p) {
    uint32_t a;
    asm("{ .reg .u64 t; cvta.to.shared.u64 t, %1; cvt.u32.u64 %0, t; }" : "=r"(a) : "l"(p));
    return a;
}
__device__ __forceinline__ void cp_async16(uint32_t dst, const void* src) {
    asm volatile("cp.async.cg.shared.global [%0], [%1], 16;" :: "r"(dst), "l"(src));
}
#define CP_COMMIT() asm volatile("cp.async.commit_group;" ::: "memory")
#define CP_WAIT(n)  asm volatile("cp.async.wait_group %0;" :: "n"(n) : "memory")

__device__ __forceinline__ void ldsm_x4(uint32_t& r0, uint32_t& r1, uint32_t& r2, uint32_t& r3,
                                        uint32_t addr) {
    asm volatile("ldmatrix.sync.aligned.m8n8.x4.shared.b16 {%0,%1,%2,%3}, [%4];"
                 : "=r"(r0), "=r"(r1), "=r"(r2), "=r"(r3) : "r"(addr));
}
__device__ __forceinline__ void mma16816(float* c, uint32_t a0, uint32_t a1, uint32_t a2,
                                         uint32_t a3, uint32_t b0, uint32_t b1) {
    asm volatile(
        "mma.sync.aligned.m16n8k16.row.col.f32.bf16.bf16.f32 "
        "{%0,%1,%2,%3}, {%4,%5,%6,%7}, {%8,%9}, {%0,%1,%2,%3};"
        : "+f"(c[0]), "+f"(c[1]), "+f"(c[2]), "+f"(c[3])
        : "r"(a0), "r"(a1), "r"(a2), "r"(a3), "r"(b0), "r"(b1));
}

__device__ __forceinline__ uint32_t pack2(__nv_bfloat16 a, __nv_bfloat16 b) {
    __nv_bfloat162 t; t.x = a; t.y = b;
    return *reinterpret_cast<uint32_t*>(&t);
}
__device__ __forceinline__ void split_bf16(float x, __nv_bfloat16& hi, __nv_bfloat16& lo) {
    hi = __float2bfloat16(x);
    lo = __float2bfloat16(x - __bfloat162float(hi));
}

// pack W [K,N] fp32 -> out [n][2K] bf16 (hi | lo)
template<int K, int N>
__device__ __forceinline__ void pack_w_body(int idx, const float* __restrict__ W,
                                            __nv_bfloat16* __restrict__ out)
{
    constexpr int kq4 = K >> 2;
    int n = idx / kq4;
    int k = (idx - n * kq4) * 4;
    __nv_bfloat16 h[4], l[4];
    #pragma unroll
    for (int i = 0; i < 4; i++)
        split_bf16(W[(size_t)(k + i) * N + n], h[i], l[i]);
    uint2 whi, wlo;
    whi.x = pack2(h[0], h[1]); whi.y = pack2(h[2], h[3]);
    wlo.x = pack2(l[0], l[1]); wlo.y = pack2(l[2], l[3]);
    __nv_bfloat16* base = out + (size_t)n * (2 * K);
    *reinterpret_cast<uint2*>(base + k)     = whi;
    *reinterpret_cast<uint2*>(base + K + k) = wlo;
}

// ---------------------------------------------------------------------------
// prep1: fused pack_x (blocks 0..4095) + pack_W1 (blocks 4096..4607)
// ---------------------------------------------------------------------------
__global__ __launch_bounds__(256)
void prep1_kernel(const float* __restrict__ X, const float* __restrict__ W1,
                  __nv_bfloat16* __restrict__ a1, __nv_bfloat16* __restrict__ b1)
{
    const int blk = blockIdx.x;
    if (blk < 4096) {
        // pack x: [4096,512] fp32 -> [4096][1024] bf16 (hi|lo)
        int idx = blk * 256 + threadIdx.x;          // MROWS * KS1/4 threads
        int r   = idx >> 8;                          // / (KS1/4 = 256)
        int kp  = (idx & 255) * 4;
        int seg = kp >> 9;                           // 0 = hi, 1 = lo
        int k   = kp & 511;
        float4 v = *reinterpret_cast<const float4*>(X + (size_t)r * D_IN + k);
        __nv_bfloat16 h0, l0, h1, l1, h2, l2, h3, l3;
        split_bf16(v.x, h0, l0); split_bf16(v.y, h1, l1);
        split_bf16(v.z, h2, l2); split_bf16(v.w, h3, l3);
        uint2 w;
        if (seg) { w.x = pack2(l0, l1); w.y = pack2(l2, l3); }
        else     { w.x = pack2(h0, h1); w.y = pack2(h2, h3); }
        *reinterpret_cast<uint2*>(a1 + (size_t)r * KS1 + kp) = w;
    } else {
        int idx = (blk - 4096) * 256 + threadIdx.x;  // D_HID * (D_IN/4) threads
        pack_w_body<D_IN, D_HID>(idx, W1, b1);
    }
}

// ---------------------------------------------------------------------------
// spline + pack A2' (blocks 0..4095) fused with pack_W2 (blocks 4096..4607)
// ---------------------------------------------------------------------------
__global__ __launch_bounds__(256)
void spline_prep2_kernel(const float* __restrict__ h,
                         const float* __restrict__ coeff,   // [1024, 18]
                         const float* __restrict__ sp_bias, // [1024]
                         __nv_bfloat16* __restrict__ a2,
                         const float* __restrict__ W2,
                         __nv_bfloat16* __restrict__ b2)
{
    const int blk = blockIdx.x;
    if (blk >= 4096) {
        int idx = (blk - 4096) * 256 + threadIdx.x;  // D_OUT * (D_HID/4) threads
        pack_w_body<D_HID, D_OUT>(idx, W2, b2);
        return;
    }
    const int row = blk;
    const int tid = threadIdx.x;
    const float* hr = h + (size_t)row * D_HID;

    float4 v = reinterpret_cast<const float4*>(hr)[tid];
    float mn = fminf(fminf(v.x, v.y), fminf(v.z, v.w));
    float mx = fmaxf(fmaxf(v.x, v.y), fmaxf(v.z, v.w));
    #pragma unroll
    for (int o = 16; o > 0; o >>= 1) {
        mn = fminf(mn, __shfl_xor_sync(0xffffffffu, mn, o));
        mx = fmaxf(mx, __shfl_xor_sync(0xffffffffu, mx, o));
    }
    __shared__ float smn[8], smx[8];
    const int w = tid >> 5, l = tid & 31;
    if (l == 0) { smn[w] = mn; smx[w] = mx; }
    __syncthreads();
    mn = smn[0]; mx = smx[0];
    #pragma unroll
    for (int i = 1; i < 8; i++) { mn = fminf(mn, smn[i]); mx = fmaxf(mx, smx[i]); }

    const float scale = 15.0f / (mx - mn + 1e-8f);
    float xv[4] = {v.x, v.y, v.z, v.w};
    __nv_bfloat16 hi[4], lo[4];
    #pragma unroll
    for (int j = 0; j < 4; j++) {
        const int n = tid * 4 + j;
        float xs = (xv[j] - mn) * scale;
        int s = (int)xs;
        s = min(s, 14);
        if (s < 0) s = 0;
        const float u  = xs - (float)s;
        const float um = 1.0f - u;
        const float u2 = u * u;
        const float u3 = u2 * u;
        const float b0 = um * um * um * (1.0f / 6.0f);
        const float b1 = (3.0f * u3 - 6.0f * u2 + 4.0f) * (1.0f / 6.0f);
        const float b2v = (-3.0f * u3 + 3.0f * u2 + 3.0f * u + 1.0f) * (1.0f / 6.0f);
        const float b3 = u3 * (1.0f / 6.0f);
        const float* c = coeff + n * 18 + s;
        float sp = fmaf(b0, __ldg(c + 0),
                   fmaf(b1, __ldg(c + 1),
                   fmaf(b2v, __ldg(c + 2),
                        b3 * __ldg(c + 3)))) + __ldg(&sp_bias[n]);
        split_bf16(sp, hi[j], lo[j]);
    }
    uint2 whi, wlo;
    whi.x = pack2(hi[0], hi[1]); whi.y = pack2(hi[2], hi[3]);
    wlo.x = pack2(lo[0], lo[1]); wlo.y = pack2(lo[2], lo[3]);
    const int n0 = tid * 4;
    __nv_bfloat16* base = a2 + (size_t)row * KS2;
    *reinterpret_cast<uint2*>(base + n0)         = whi;   // hi
    *reinterpret_cast<uint2*>(base + D_HID + n0) = wlo;   // lo
}

// ---------------------------------------------------------------------------
// bf16 mma.sync GEMM over dedup [hi|lo] storage.
// Augmented K' = 3K realized via kb -> source-offset remap (H = NK/3):
//   A: kb in [0,2H) linear (hi then lo); [2H,3H) -> hi again
//   B: kb in [0,H) hi; [H,2H) -> hi again; [2H,3H) -> lo
// Products: hi.hi, lo.hi, hi.lo — identical terms/order to measured r13 kernel.
// 256 threads = 8 warps (4M x 2N), BK=64, 3-stage cp.async ring, one sync/iter.
// ---------------------------------------------------------------------------
template<int NK, int BN, bool RELU>
__global__ void __launch_bounds__(256, 2)
gemm_mma(const __nv_bfloat16* __restrict__ Apk,
         const __nv_bfloat16* __restrict__ Bpk,
         const float* __restrict__ bias,
         float* __restrict__ C, int ldc)
{
    constexpr int HB   = NK / 3;
    constexpr int KPB  = 2 * HB * 128;       // bytes per packed row (2K * 2B)
    constexpr int ROWB = 144;                // padded smem row bytes
    constexpr int ASTG = 128 * ROWB;
    constexpr int BSTG = BN * ROWB;
    constexpr int STG  = ASTG + BSTG;
    constexpr int NT   = BN / 16;            // per-warp n sub-blocks

    extern __shared__ char smem[];
    const uint32_t sb = smem_u32(smem);

    const int tid  = threadIdx.x;
    const int wid  = tid >> 5;
    const int lane = tid & 31;
    const int wm   = wid & 3;
    const int wn   = wid >> 2;

    const char* Ag = (const char*)Apk + (size_t)(blockIdx.y * 128) * KPB;
    const char* Bg = (const char*)Bpk + (size_t)(blockIdx.x * BN) * KPB;

    auto load_stage = [&](int kb, int s) {
        const uint32_t as = sb + s * STG;
        const uint32_t bs = as + ASTG;
        const int ka  = (kb < 2 * HB ? kb : kb - 2 * HB) * 128;  // A src byte off
        const int kbo = (kb < HB     ? kb : kb - HB)     * 128;  // B src byte off
        #pragma unroll
        for (int i = 0; i < 4; i++) {        // A: 1024 chunks of 16B
            int idx = i * 256 + tid;
            int row = idx >> 3, ch = idx & 7;
            cp_async16(as + row * ROWB + ch * 16,
                       Ag + (size_t)row * KPB + ka + ch * 16);
        }
        #pragma unroll
        for (int i = 0; i < BN / 32; i++) {  // B: BN*8 chunks of 16B
            int idx = i * 256 + tid;
            int row = idx >> 3, ch = idx & 7;
            cp_async16(bs + row * ROWB + ch * 16,
                       Bg + (size_t)row * KPB + kbo + ch * 16);
        }
    };

    float acc[2][NT][4];
    #pragma unroll
    for (int i = 0; i < 2; i++)
        #pragma unroll
        for (int j = 0; j < NT; j++)
            #pragma unroll
            for (int t = 0; t < 4; t++) acc[i][j][t] = 0.0f;

    load_stage(0, 0);
    CP_COMMIT();
    load_stage(1, 1);
    CP_COMMIT();

    const int a_lrow = lane & 15;
    const int a_lcb  = (lane >> 4) * 16;
    const int b_sub  = lane >> 3;
    const int b_noff = ((b_sub >> 1) << 3) + (lane & 7);
    const int b_kb   = (b_sub & 1) * 16;

    for (int kb = 0; kb < NK; kb++) {
        if (kb + 1 < NK) { CP_WAIT(1); } else { CP_WAIT(0); }
        __syncthreads();

        const int s = kb % 3;
        const uint32_t as = sb + s * STG;
        const uint32_t bs = as + ASTG;

        if (kb + 2 < NK) {
            load_stage(kb + 2, (kb + 2) % 3);
            CP_COMMIT();
        }

        #pragma unroll
        for (int k0 = 0; k0 < 64; k0 += 16) {
            uint32_t a[2][4];
            #pragma unroll
            for (int mt = 0; mt < 2; mt++) {
                uint32_t addr = as + (wm * 32 + mt * 16 + a_lrow) * ROWB + k0 * 2 + a_lcb;
                ldsm_x4(a[mt][0], a[mt][1], a[mt][2], a[mt][3], addr);
            }
            uint32_t b[NT][2];
            #pragma unroll
            for (int p = 0; p < NT / 2; p++) {
                uint32_t addr = bs + (wn * (8 * NT) + p * 16 + b_noff) * ROWB + k0 * 2 + b_kb;
                ldsm_x4(b[p * 2][0], b[p * 2][1], b[p * 2 + 1][0], b[p * 2 + 1][1], addr);
            }
            #pragma unroll
            for (int mt = 0; mt < 2; mt++)
                #pragma unroll
                for (int nt = 0; nt < NT; nt++)
                    mma16816(acc[mt][nt], a[mt][0], a[mt][1], a[mt][2], a[mt][3],
                             b[nt][0], b[nt][1]);
        }
    }

    const int g  = lane >> 2;
    const int tg = lane & 3;
    #pragma unroll
    for (int mt = 0; mt < 2; mt++) {
        const int row0 = blockIdx.y * 128 + wm * 32 + mt * 16 + g;
        #pragma unroll
        for (int nt = 0; nt < NT; nt++) {
            const int col = blockIdx.x * BN + wn * (8 * NT) + nt * 8 + tg * 2;
            float2 bv = *reinterpret_cast<const float2*>(bias + col);
            float2 o0, o1;
            o0.x = acc[mt][nt][0] + bv.x; o0.y = acc[mt][nt][1] + bv.y;
            o1.x = acc[mt][nt][2] + bv.x; o1.y = acc[mt][nt][3] + bv.y;
            if (RELU) {
                o0.x = fmaxf(o0.x, 0.0f); o0.y = fmaxf(o0.y, 0.0f);
                o1.x = fmaxf(o1.x, 0.0f); o1.y = fmaxf(o1.y, 0.0f);
            }
            *reinterpret_cast<float2*>(C + (size_t)row0 * ldc + col)       = o0;
            *reinterpret_cast<float2*>(C + (size_t)(row0 + 8) * ldc + col) = o1;
        }
    }
}

// ---------------------------------------------------------------------------
extern "C" void kernel_launch(void* const* d_in, const int* in_sizes, int n_in,
                              void* d_out, int out_size)
{
    const float* x       = (const float*)d_in[0];
    const float* W1      = (const float*)d_in[1];
    const float* b1      = (const float*)d_in[2];
    const float* coeff   = (const float*)d_in[3];
    const float* sp_bias = (const float*)d_in[4];
    const float* W2      = (const float*)d_in[5];
    const float* b2      = (const float*)d_in[6];
    float* out = (float*)d_out;

    __nv_bfloat16 *a1, *bp1, *a2, *bp2;
    float* h_ptr;
    cudaGetSymbolAddress((void**)&a1,    g_a1);
    cudaGetSymbolAddress((void**)&bp1,   g_b1);
    cudaGetSymbolAddress((void**)&h_ptr, g_h);
    cudaGetSymbolAddress((void**)&a2,    g_a2);
    cudaGetSymbolAddress((void**)&bp2,   g_b2);

    constexpr int SMEM1 = 3 * (128 * 144 + 128 * 144);  // 110592 (BN=128)
    constexpr int SMEM2 = 3 * (128 * 144 + 64 * 144);   // 82944  (BN=64)
    cudaFuncSetAttribute(gemm_mma<NK1, 128, false>,
                         cudaFuncAttributeMaxDynamicSharedMemorySize, SMEM1);
    cudaFuncSetAttribute(gemm_mma<NK2, 64, true>,
                         cudaFuncAttributeMaxDynamicSharedMemorySize, SMEM2);

    // prep: pack x (4096 blocks) + pack W1 (512 blocks) fused
    prep1_kernel<<<4096 + 512, 256>>>(x, W1, a1, bp1);

    // GEMM1: h = x @ W1 + b1   (M=4096, N=1024, K'=1536 via remap)
    {
        dim3 grid(D_HID / 128, MROWS / 128);
        gemm_mma<NK1, 128, false><<<grid, 256, SMEM1>>>(a1, bp1, b1, h_ptr, D_HID);
    }
    // norm + spline + pack A2' (4096 blocks) fused with pack W2 (512 blocks)
    spline_prep2_kernel<<<4096 + 512, 256>>>(h_ptr, coeff, sp_bias, a2, W2, bp2);
    // GEMM2: out = relu(sp @ W2 + b2)  (M=4096, N=512, K'=3072 via remap)
    {
        dim3 grid(D_OUT / 64, MROWS / 128);
        gemm_mma<NK2, 64, true><<<grid, 256, SMEM2>>>(a2, bp2, b2, out, D_OUT);
    }
}